// round 6
// baseline (speedup 1.0000x reference)
#include <cuda_runtime.h>

typedef unsigned long long u64;

// ---------------- scratch (device globals; no allocation) ----------------
__device__ float g_pre[16*64*1024];     // conv1 out, then h (in-place)
__device__ float2 g_bstats[64*16];      // per (oc,b) partial {sum, sumsq}
__device__ float g_S[16*64*9];          // 9 shifted window sums per (b, in-ch)
__device__ float g_Q[16*4*1024*10];
__device__ float g_KV[16*4*1024*20];    // interleaved K(10) | V(10) per key
__device__ float g_pA[2*16*4*1024*10];  // unnormalized attn partials (2 key-chunks)
__device__ float g_pl[2*16*4*1024];     // softmax denominators (partial)

__device__ __forceinline__ float wred(float v) {
  #pragma unroll
  for (int o = 16; o; o >>= 1) v += __shfl_down_sync(0xffffffffu, v, o);
  return v;
}

// ---- packed f32x2 helpers (sm_100+) ----
__device__ __forceinline__ u64 ffma2(u64 a, u64 b, u64 c) {
  u64 d; asm("fma.rn.f32x2 %0, %1, %2, %3;" : "=l"(d) : "l"(a), "l"(b), "l"(c)); return d;
}
__device__ __forceinline__ u64 fmul2(u64 a, u64 b) {
  u64 d; asm("mul.rn.f32x2 %0, %1, %2;" : "=l"(d) : "l"(a), "l"(b)); return d;
}
__device__ __forceinline__ u64 pack2(float lo, float hi) {
  u64 r; asm("mov.b64 %0, {%1, %2};" : "=l"(r) : "f"(lo), "f"(hi)); return r;
}
__device__ __forceinline__ float2 unpack2(u64 v) {
  float lo, hi; asm("mov.b64 {%0, %1}, %2;" : "=f"(lo), "=f"(hi) : "l"(v));
  return make_float2(lo, hi);
}
__device__ __forceinline__ float ex2f(float x) {
  float y; asm("ex2.approx.f32 %0, %1;" : "=f"(y) : "f"(x)); return y;
}

union F4U { float4 f4; ulonglong2 u2; };
union F2U { float2 f2; u64 u; };

__device__ __forceinline__ u64 ldf2(const float* p) {
  F2U t; t.f2 = *(const float2*)p; return t.u;
}

// ---------------- K0: conv1 3x3 (3->64) SAME + per-block BN partial stats ----------------
__global__ void __launch_bounds__(256) conv1_kernel(const float* __restrict__ x,
                                                    const float* __restrict__ w,
                                                    const float* __restrict__ bias) {
  int t = threadIdx.x;
  int oc = blockIdx.x, b = blockIdx.y;
  int p0 = t * 4;
  int y = p0 >> 5, x0 = p0 & 31;
  float w_[27];
  #pragma unroll
  for (int i = 0; i < 27; i++) w_[i] = __ldg(&w[oc * 27 + i]);
  float bv = __ldg(&bias[oc]);
  float a0 = bv, a1 = bv, a2 = bv, a3 = bv;
  #pragma unroll
  for (int ic = 0; ic < 3; ic++) {
    const float* base = x + (b * 3 + ic) * 1024;
    #pragma unroll
    for (int ky = 0; ky < 3; ky++) {
      int iy = y + ky - 1;
      if (iy < 0 || iy > 31) continue;
      const float* row = base + iy * 32;
      float r[6];
      #pragma unroll
      for (int dx = 0; dx < 6; dx++) {
        int c = x0 - 1 + dx;
        r[dx] = (c >= 0 && c < 32) ? __ldg(&row[c]) : 0.f;
      }
      #pragma unroll
      for (int kx = 0; kx < 3; kx++) {
        float wv = w_[ic * 9 + ky * 3 + kx];
        a0 = fmaf(wv, r[kx],     a0);
        a1 = fmaf(wv, r[kx + 1], a1);
        a2 = fmaf(wv, r[kx + 2], a2);
        a3 = fmaf(wv, r[kx + 3], a3);
      }
    }
  }
  *(float4*)(g_pre + (b * 64 + oc) * 1024 + p0) = make_float4(a0, a1, a2, a3);

  float s  = a0 + a1 + a2 + a3;
  float sq = fmaf(a0, a0, fmaf(a1, a1, fmaf(a2, a2, a3 * a3)));
  s = wred(s); sq = wred(sq);
  __shared__ float ss[8], s2m[8];
  int warp = t >> 5, lane = t & 31;
  if (lane == 0) { ss[warp] = s; s2m[warp] = sq; }
  __syncthreads();
  if (t == 0) {
    float S = 0.f, Q = 0.f;
    #pragma unroll
    for (int i = 0; i < 8; i++) { S += ss[i]; Q += s2m[i]; }
    g_bstats[oc * 16 + b] = make_float2(S, Q);
  }
}

// ---------------- K1: BN finalize + apply + relu (in place) + 9 window sums ----------------
__global__ void bnrelu_kernel(const float* __restrict__ gamma,
                              const float* __restrict__ beta) {
  int c = blockIdx.x, b = blockIdx.y;
  int p = threadIdx.x;                  // 1024 threads
  __shared__ float scb[2];
  if (p < 16) {
    float2 v = g_bstats[c * 16 + p];
    float s = v.x, q = v.y;
    #pragma unroll
    for (int o = 8; o; o >>= 1) {
      s += __shfl_down_sync(0xffffu, s, o, 16);
      q += __shfl_down_sync(0xffffu, q, o, 16);
    }
    if (p == 0) {
      float mean = s * (1.f / 16384.f);
      float var  = q * (1.f / 16384.f) - mean * mean;
      float sc = __ldg(&gamma[c]) * rsqrtf(var + 1e-5f);
      scb[0] = sc;
      scb[1] = __ldg(&beta[c]) - mean * sc;
    }
  }
  __syncthreads();

  int y = p >> 5, xx = p & 31;
  int idx = (b * 64 + c) * 1024 + p;
  float v = fmaxf(fmaf(g_pre[idx], scb[0], scb[1]), 0.f);
  g_pre[idx] = v;

  float t = v;
  float r0  = (y == 0)  ? v : 0.f;
  float r31 = (y == 31) ? v : 0.f;
  float c0  = (xx == 0)  ? v : 0.f;
  float c31 = (xx == 31) ? v : 0.f;

  __shared__ float red[32][5];
  __shared__ float corn[4];
  if (p == 0)    corn[0] = v;
  if (p == 31)   corn[1] = v;
  if (p == 992)  corn[2] = v;
  if (p == 1023) corn[3] = v;

  t = wred(t); r0 = wred(r0); r31 = wred(r31); c0 = wred(c0); c31 = wred(c31);
  int warp = p >> 5, lane = p & 31;
  if (lane == 0) { red[warp][0]=t; red[warp][1]=r0; red[warp][2]=r31; red[warp][3]=c0; red[warp][4]=c31; }
  __syncthreads();
  if (p < 32) {
    float a0 = red[p][0], a1 = red[p][1], a2 = red[p][2], a3 = red[p][3], a4 = red[p][4];
    a0 = wred(a0); a1 = wred(a1); a2 = wred(a2); a3 = wred(a3); a4 = wred(a4);
    if (p == 0) {
      float T = a0, R0 = a1, R31 = a2, C0 = a3, C31 = a4;
      float* Sp = g_S + (b * 64 + c) * 9;
      Sp[0] = T - R31 - C31 + corn[3];
      Sp[1] = T - R31;
      Sp[2] = T - R31 - C0 + corn[2];
      Sp[3] = T - C31;
      Sp[4] = T;
      Sp[5] = T - C0;
      Sp[6] = T - R0 - C31 + corn[1];
      Sp[7] = T - R0;
      Sp[8] = T - R0 - C0 + corn[0];
    }
  }
}

// ---------------- K2: qkv 1x1 conv -> Q (scaled), KV interleaved ----------------
__global__ void __launch_bounds__(256) qkv_kernel(const float* __restrict__ w,
                                                  const float* __restrict__ bias) {
  int tid = threadIdx.x;        // 256
  int b = blockIdx.z;
  int o0 = blockIdx.y * 8;      // 15 groups of 8 output channels
  __shared__ float ws[512];
  __shared__ float bs[8];
  for (int i = tid; i < 512; i += 256) ws[i] = w[o0 * 64 + i];
  if (tid < 8) bs[tid] = bias[o0 + tid];
  __syncthreads();
  int n0 = tid * 4;
  float4 acc[8];
  #pragma unroll
  for (int u = 0; u < 8; u++) { float bv = bs[u]; acc[u] = make_float4(bv, bv, bv, bv); }
  const float* hp = g_pre + b * 64 * 1024 + n0;
  #pragma unroll 4
  for (int i = 0; i < 64; i++) {
    float4 hv = *(const float4*)(hp + i * 1024);
    #pragma unroll
    for (int u = 0; u < 8; u++) {
      float wv = ws[u * 64 + i];
      acc[u].x = fmaf(wv, hv.x, acc[u].x);
      acc[u].y = fmaf(wv, hv.y, acc[u].y);
      acc[u].z = fmaf(wv, hv.z, acc[u].z);
      acc[u].w = fmaf(wv, hv.w, acc[u].w);
    }
  }
  // Q gets dkh^-0.5 * log2(e) folded in (exp -> ex2 domain; exact)
  const float QMUL = 0.31622776601683794f * 1.4426950408889634f;
  #pragma unroll
  for (int u = 0; u < 8; u++) {
    int o = o0 + u;
    int which = o / 40;
    int r = o - which * 40;
    int head = r / 10, d = r - head * 10;
    int bh = b * 4 + head;
    if (which == 0) {
      float* pb = g_Q + (bh * 1024) * 10 + d;
      pb[(n0 + 0) * 10] = acc[u].x * QMUL;
      pb[(n0 + 1) * 10] = acc[u].y * QMUL;
      pb[(n0 + 2) * 10] = acc[u].z * QMUL;
      pb[(n0 + 3) * 10] = acc[u].w * QMUL;
    } else {
      float* pb = g_KV + (bh * 1024) * 20 + ((which == 1) ? d : 10 + d);
      pb[(n0 + 0) * 20] = acc[u].x;
      pb[(n0 + 1) * 20] = acc[u].y;
      pb[(n0 + 2) * 20] = acc[u].z;
      pb[(n0 + 3) * 20] = acc[u].w;
    }
  }
}

// ---------------- K3: attention, split-K (2 chunks of 512 keys), 1 query/thread ----------------
// smem: KV chunk 512*20 (40960B) + krh 630 + krw 630
#define ATTN_SMEM ((10240 + 640 + 640) * 4)

__global__ void __launch_bounds__(256, 2) attn_kernel(const float* __restrict__ krh,
                                                      const float* __restrict__ krw) {
  extern __shared__ float sm[];
  float* KVs = sm;               // [512][20]
  float* Hs  = sm + 10240;       // key_rel_h 63*10
  float* Ws  = sm + 10880;       // key_rel_w 63*10
  int bh = blockIdx.z;
  int kc = blockIdx.y;           // key chunk 0/1
  int tid = threadIdx.x;         // 256
  int warp = tid >> 5, lane = tid & 31;

  // stage KV chunk (coalesced float4 copy) + rel tables
  {
    const float4* src = (const float4*)(g_KV + bh * 20480 + kc * 10240);
    float4* dst = (float4*)KVs;
    #pragma unroll 10
    for (int i = tid; i < 2560; i += 256) dst[i] = src[i];
    for (int i = tid; i < 630; i += 256) { Hs[i] = krh[i]; Ws[i] = krw[i]; }
  }

  int yq = blockIdx.x * 8 + warp;   // warp = one query row
  int xq = lane;
  int n = yq * 32 + xq;
  const float* qp = g_Q + (bh * 1024 + n) * 10;   // pre-scaled by dkh^-.5*log2e
  u64 Q01 = ldf2(qp), Q23 = ldf2(qp + 2), Q45 = ldf2(qp + 4),
      Q67 = ldf2(qp + 6), Q89 = ldf2(qp + 8);

  __syncthreads();

  // rw[xm] = q . key_rel_w[xm - xq + 31]  (log2e domain)
  float rw[32];
  #pragma unroll
  for (int xm = 0; xm < 32; xm++) {
    const float* kr = Ws + (xm - xq + 31) * 10;
    u64 s2 = fmul2(Q01, ldf2(kr));
    s2 = ffma2(Q23, ldf2(kr + 2), s2);
    s2 = ffma2(Q45, ldf2(kr + 4), s2);
    s2 = ffma2(Q67, ldf2(kr + 6), s2);
    s2 = ffma2(Q89, ldf2(kr + 8), s2);
    float2 sp = unpack2(s2);
    rw[xm] = sp.x + sp.y;
  }

  u64 A01 = 0, A23 = 0, A45 = 0, A67 = 0, A89 = 0;
  float l = 0.f;
  #pragma unroll 1
  for (int ym16 = 0; ym16 < 16; ym16++) {
    int ymg = kc * 16 + ym16;
    const float* kh = Hs + (ymg - yq + 31) * 10;   // smem broadcast (yq const per warp)
    u64 r2 = fmul2(Q01, ldf2(kh));
    r2 = ffma2(Q23, ldf2(kh + 2), r2);
    r2 = ffma2(Q45, ldf2(kh + 4), r2);
    r2 = ffma2(Q67, ldf2(kh + 6), r2);
    r2 = ffma2(Q89, ldf2(kh + 8), r2);
    float2 rr = unpack2(r2);
    float rh = rr.x + rr.y;

    const float4* kv = (const float4*)(KVs + ym16 * 640);
    #pragma unroll
    for (int xm = 0; xm < 32; xm++) {
      F4U c0, c1, c2, c3, c4;
      c0.f4 = kv[xm * 5];      // K0..K3
      c1.f4 = kv[xm * 5 + 1];  // K4..K7
      c2.f4 = kv[xm * 5 + 2];  // K8,K9,V0,V1
      c3.f4 = kv[xm * 5 + 3];  // V2..V5
      c4.f4 = kv[xm * 5 + 4];  // V6..V9
      u64 s2 = ffma2(Q01, c0.u2.x, pack2(rh, rw[xm]));
      s2 = ffma2(Q23, c0.u2.y, s2);
      s2 = ffma2(Q45, c1.u2.x, s2);
      s2 = ffma2(Q67, c1.u2.y, s2);
      s2 = ffma2(Q89, c2.u2.x, s2);
      float2 sp = unpack2(s2);
      float p = ex2f(sp.x + sp.y);     // logits tiny; no max-subtract needed
      l += p;
      u64 P = pack2(p, p);
      A01 = ffma2(P, c2.u2.y, A01);
      A23 = ffma2(P, c3.u2.x, A23);
      A45 = ffma2(P, c3.u2.y, A45);
      A67 = ffma2(P, c4.u2.x, A67);
      A89 = ffma2(P, c4.u2.y, A89);
    }
  }
  // store unnormalized partials (normalization happens in final_kernel)
  u64* op = (u64*)(g_pA + ((kc * 64 + bh) * 1024 + n) * 10);
  op[0] = A01; op[1] = A23; op[2] = A45; op[3] = A67; op[4] = A89;
  g_pl[(kc * 64 + bh) * 1024 + n] = l;
}

// ---------------- K4: combine partials + poolconv + attno + fc ----------------
__global__ void final_kernel(const float* __restrict__ convo_w,
                             const float* __restrict__ convo_b,
                             const float* __restrict__ attno_w,
                             const float* __restrict__ attno_b,
                             const float* __restrict__ fc_w,
                             const float* __restrict__ fc_b,
                             float* __restrict__ out) {
  int b = blockIdx.x, tid = threadIdx.x;  // 256 threads
  int warp = tid >> 5, lane = tid & 31;
  __shared__ float Ssm[576];
  __shared__ float invl[4096];   // per (head,n) 1/(l0+l1)
  __shared__ float pooled[88];
  __shared__ float mean_s[40], pa[40];

  for (int i = tid; i < 576; i += 256) Ssm[i] = g_S[b * 576 + i];
  // softmax denominators: bh*1024+n = b*4096 + i
  #pragma unroll 4
  for (int i = tid; i < 4096; i += 256) {
    float l0 = g_pl[b * 4096 + i];
    float l1 = g_pl[64 * 1024 + b * 4096 + i];
    invl[i] = __frcp_rn(l0 + l1);
  }
  __syncthreads();

  // pooled conv_out: 88 channels, warp per channel (8 warps x 11)
  #pragma unroll
  for (int i = 0; i < 11; i++) {
    int oc = warp * 11 + i;
    float acc = 0.f;
    const float* wp = convo_w + oc * 576;
    #pragma unroll
    for (int j = lane; j < 576; j += 32) acc = fmaf(__ldg(&wp[j]), Ssm[j], acc);
    acc = wred(acc);
    if (lane == 0) pooled[oc] = __ldg(&convo_b[oc]) + acc * (1.f / 1024.f);
  }

  // attn channel means over (n,d)-flat: channel c = flat[c*1024 .. c*1024+1023]
  // flat f within b: head = f/10240, n, d; invl index = f/10.
  #pragma unroll
  for (int cc = 0; cc < 5; cc++) {
    int c = warp * 5 + cc;
    const float* pA0 = g_pA + b * 40960 + c * 1024;
    const float* pA1 = g_pA + 64 * 10240 + b * 40960 + c * 1024;
    int fbase = c * 1024;
    float s = 0.f;
    #pragma unroll 4
    for (int j = lane; j < 1024; j += 32) {
      float a = pA0[j] + pA1[j];
      s = fmaf(a, invl[(fbase + j) / 10], s);
    }
    s = wred(s);
    if (lane == 0) mean_s[c] = s * (1.f / 1024.f);
  }
  __syncthreads();
  if (tid < 40) {
    float acc = __ldg(&attno_b[tid]);
    #pragma unroll 4
    for (int c = 0; c < 40; c++) acc = fmaf(__ldg(&attno_w[tid * 40 + c]), mean_s[c], acc);
    pa[tid] = acc;
  }
  __syncthreads();
  if (tid < 100) {
    float acc = __ldg(&fc_b[tid]);
    const float* wp = fc_w + tid * 128;
    #pragma unroll 4
    for (int c = 0; c < 88; c++) acc = fmaf(__ldg(&wp[c]), pooled[c], acc);
    #pragma unroll 4
    for (int c = 0; c < 40; c++) acc = fmaf(__ldg(&wp[88 + c]), pa[c], acc);
    out[b * 100 + tid] = acc;
  }
}

// ---------------- launch ----------------
extern "C" void kernel_launch(void* const* d_in, const int* in_sizes, int n_in,
                              void* d_out, int out_size) {
  const float* x         = (const float*)d_in[0];
  const float* conv1_w   = (const float*)d_in[1];
  const float* conv1_b   = (const float*)d_in[2];
  const float* bn1_g     = (const float*)d_in[3];
  const float* bn1_b     = (const float*)d_in[4];
  const float* convo_w   = (const float*)d_in[5];
  const float* convo_b   = (const float*)d_in[6];
  const float* qkv_w     = (const float*)d_in[7];
  const float* qkv_b     = (const float*)d_in[8];
  const float* attno_w   = (const float*)d_in[9];
  const float* attno_b   = (const float*)d_in[10];
  const float* key_rel_h = (const float*)d_in[11];
  const float* key_rel_w = (const float*)d_in[12];
  const float* fc_w      = (const float*)d_in[13];
  const float* fc_b      = (const float*)d_in[14];
  float* out = (float*)d_out;

  cudaFuncSetAttribute(attn_kernel, cudaFuncAttributeMaxDynamicSharedMemorySize, ATTN_SMEM);

  conv1_kernel<<<dim3(64, 16), 256>>>(x, conv1_w, conv1_b);     // #0
  bnrelu_kernel<<<dim3(64, 16), 1024>>>(bn1_g, bn1_b);          // #1
  qkv_kernel<<<dim3(1, 15, 16), 256>>>(qkv_w, qkv_b);           // #2
  attn_kernel<<<dim3(4, 2, 64), 256, ATTN_SMEM>>>(key_rel_h, key_rel_w);  // #3 (profiled)
  final_kernel<<<16, 256>>>(convo_w, convo_b, attno_w, attno_b, fc_w, fc_b, out);
}

// round 7
// speedup vs baseline: 1.0199x; 1.0199x over previous
#include <cuda_runtime.h>

typedef unsigned long long u64;

// ---------------- scratch (device globals; no allocation) ----------------
__device__ float g_pre[16*64*1024];     // conv1 out, then h (in-place)
__device__ float2 g_bstats[64*16];      // per (oc,b) partial {sum, sumsq}
__device__ float g_S[16*64*9];          // 9 shifted window sums per (b, in-ch)
__device__ float g_Q[16*4*1024*10];
__device__ float g_KV[16*4*1024*20];    // interleaved K(10) | V(10) per key
__device__ float g_pA[2*16*4*1024*10];  // unnormalized attn partials (2 key-chunks)
__device__ float g_pl[2*16*4*1024];     // softmax denominators (partial)

__device__ __forceinline__ float wred(float v) {
  #pragma unroll
  for (int o = 16; o; o >>= 1) v += __shfl_down_sync(0xffffffffu, v, o);
  return v;
}

// ---- packed f32x2 helpers (sm_100+) ----
__device__ __forceinline__ u64 ffma2(u64 a, u64 b, u64 c) {
  u64 d; asm("fma.rn.f32x2 %0, %1, %2, %3;" : "=l"(d) : "l"(a), "l"(b), "l"(c)); return d;
}
__device__ __forceinline__ u64 fmul2(u64 a, u64 b) {
  u64 d; asm("mul.rn.f32x2 %0, %1, %2;" : "=l"(d) : "l"(a), "l"(b)); return d;
}
__device__ __forceinline__ u64 pack2(float lo, float hi) {
  u64 r; asm("mov.b64 %0, {%1, %2};" : "=l"(r) : "f"(lo), "f"(hi)); return r;
}
__device__ __forceinline__ float2 unpack2(u64 v) {
  float lo, hi; asm("mov.b64 {%0, %1}, %2;" : "=f"(lo), "=f"(hi) : "l"(v));
  return make_float2(lo, hi);
}
__device__ __forceinline__ float ex2f(float x) {
  float y; asm("ex2.approx.f32 %0, %1;" : "=f"(y) : "f"(x)); return y;
}

union F4U { float4 f4; ulonglong2 u2; };
union F2U { float2 f2; u64 u; };

__device__ __forceinline__ u64 ldf2(const float* p) {
  F2U t; t.f2 = *(const float2*)p; return t.u;
}

// ---------------- K0: conv1 3x3 (3->64) SAME + per-block BN partial stats ----------------
__global__ void __launch_bounds__(256) conv1_kernel(const float* __restrict__ x,
                                                    const float* __restrict__ w,
                                                    const float* __restrict__ bias) {
  int t = threadIdx.x;
  int oc = blockIdx.x, b = blockIdx.y;
  int p0 = t * 4;
  int y = p0 >> 5, x0 = p0 & 31;
  float w_[27];
  #pragma unroll
  for (int i = 0; i < 27; i++) w_[i] = __ldg(&w[oc * 27 + i]);
  float bv = __ldg(&bias[oc]);
  float a0 = bv, a1 = bv, a2 = bv, a3 = bv;
  #pragma unroll
  for (int ic = 0; ic < 3; ic++) {
    const float* base = x + (b * 3 + ic) * 1024;
    #pragma unroll
    for (int ky = 0; ky < 3; ky++) {
      int iy = y + ky - 1;
      if (iy < 0 || iy > 31) continue;
      const float* row = base + iy * 32;
      float r[6];
      #pragma unroll
      for (int dx = 0; dx < 6; dx++) {
        int c = x0 - 1 + dx;
        r[dx] = (c >= 0 && c < 32) ? __ldg(&row[c]) : 0.f;
      }
      #pragma unroll
      for (int kx = 0; kx < 3; kx++) {
        float wv = w_[ic * 9 + ky * 3 + kx];
        a0 = fmaf(wv, r[kx],     a0);
        a1 = fmaf(wv, r[kx + 1], a1);
        a2 = fmaf(wv, r[kx + 2], a2);
        a3 = fmaf(wv, r[kx + 3], a3);
      }
    }
  }
  *(float4*)(g_pre + (b * 64 + oc) * 1024 + p0) = make_float4(a0, a1, a2, a3);

  float s  = a0 + a1 + a2 + a3;
  float sq = fmaf(a0, a0, fmaf(a1, a1, fmaf(a2, a2, a3 * a3)));
  s = wred(s); sq = wred(sq);
  __shared__ float ss[8], s2m[8];
  int warp = t >> 5, lane = t & 31;
  if (lane == 0) { ss[warp] = s; s2m[warp] = sq; }
  __syncthreads();
  if (t == 0) {
    float S = 0.f, Q = 0.f;
    #pragma unroll
    for (int i = 0; i < 8; i++) { S += ss[i]; Q += s2m[i]; }
    g_bstats[oc * 16 + b] = make_float2(S, Q);
  }
}

// ---------------- K1: BN finalize + apply + relu (in place) + 9 window sums ----------------
__global__ void bnrelu_kernel(const float* __restrict__ gamma,
                              const float* __restrict__ beta) {
  int c = blockIdx.x, b = blockIdx.y;
  int p = threadIdx.x;                  // 1024 threads
  __shared__ float scb[2];
  if (p < 16) {
    float2 v = g_bstats[c * 16 + p];
    float s = v.x, q = v.y;
    #pragma unroll
    for (int o = 8; o; o >>= 1) {
      s += __shfl_down_sync(0xffffu, s, o, 16);
      q += __shfl_down_sync(0xffffu, q, o, 16);
    }
    if (p == 0) {
      float mean = s * (1.f / 16384.f);
      float var  = q * (1.f / 16384.f) - mean * mean;
      float sc = __ldg(&gamma[c]) * rsqrtf(var + 1e-5f);
      scb[0] = sc;
      scb[1] = __ldg(&beta[c]) - mean * sc;
    }
  }
  __syncthreads();

  int y = p >> 5, xx = p & 31;
  int idx = (b * 64 + c) * 1024 + p;
  float v = fmaxf(fmaf(g_pre[idx], scb[0], scb[1]), 0.f);
  g_pre[idx] = v;

  float t = v;
  float r0  = (y == 0)  ? v : 0.f;
  float r31 = (y == 31) ? v : 0.f;
  float c0  = (xx == 0)  ? v : 0.f;
  float c31 = (xx == 31) ? v : 0.f;

  __shared__ float red[32][5];
  __shared__ float corn[4];
  if (p == 0)    corn[0] = v;
  if (p == 31)   corn[1] = v;
  if (p == 992)  corn[2] = v;
  if (p == 1023) corn[3] = v;

  t = wred(t); r0 = wred(r0); r31 = wred(r31); c0 = wred(c0); c31 = wred(c31);
  int warp = p >> 5, lane = p & 31;
  if (lane == 0) { red[warp][0]=t; red[warp][1]=r0; red[warp][2]=r31; red[warp][3]=c0; red[warp][4]=c31; }
  __syncthreads();
  if (p < 32) {
    float a0 = red[p][0], a1 = red[p][1], a2 = red[p][2], a3 = red[p][3], a4 = red[p][4];
    a0 = wred(a0); a1 = wred(a1); a2 = wred(a2); a3 = wred(a3); a4 = wred(a4);
    if (p == 0) {
      float T = a0, R0 = a1, R31 = a2, C0 = a3, C31 = a4;
      float* Sp = g_S + (b * 64 + c) * 9;
      Sp[0] = T - R31 - C31 + corn[3];
      Sp[1] = T - R31;
      Sp[2] = T - R31 - C0 + corn[2];
      Sp[3] = T - C31;
      Sp[4] = T;
      Sp[5] = T - C0;
      Sp[6] = T - R0 - C31 + corn[1];
      Sp[7] = T - R0;
      Sp[8] = T - R0 - C0 + corn[0];
    }
  }
}

// ---------------- K2: qkv 1x1 conv -> Q (scaled), KV interleaved ----------------
__global__ void __launch_bounds__(256) qkv_kernel(const float* __restrict__ w,
                                                  const float* __restrict__ bias) {
  int tid = threadIdx.x;        // 256
  int b = blockIdx.z;
  int o0 = blockIdx.y * 8;      // 15 groups of 8 output channels
  __shared__ float ws[512];
  __shared__ float bs[8];
  for (int i = tid; i < 512; i += 256) ws[i] = w[o0 * 64 + i];
  if (tid < 8) bs[tid] = bias[o0 + tid];
  __syncthreads();
  int n0 = tid * 4;
  float4 acc[8];
  #pragma unroll
  for (int u = 0; u < 8; u++) { float bv = bs[u]; acc[u] = make_float4(bv, bv, bv, bv); }
  const float* hp = g_pre + b * 64 * 1024 + n0;
  #pragma unroll 4
  for (int i = 0; i < 64; i++) {
    float4 hv = *(const float4*)(hp + i * 1024);
    #pragma unroll
    for (int u = 0; u < 8; u++) {
      float wv = ws[u * 64 + i];
      acc[u].x = fmaf(wv, hv.x, acc[u].x);
      acc[u].y = fmaf(wv, hv.y, acc[u].y);
      acc[u].z = fmaf(wv, hv.z, acc[u].z);
      acc[u].w = fmaf(wv, hv.w, acc[u].w);
    }
  }
  // Q gets dkh^-0.5 * log2(e) folded in (exp -> ex2 domain; exact)
  const float QMUL = 0.31622776601683794f * 1.4426950408889634f;
  #pragma unroll
  for (int u = 0; u < 8; u++) {
    int o = o0 + u;
    int which = o / 40;
    int r = o - which * 40;
    int head = r / 10, d = r - head * 10;
    int bh = b * 4 + head;
    if (which == 0) {
      float* pb = g_Q + (bh * 1024) * 10 + d;
      pb[(n0 + 0) * 10] = acc[u].x * QMUL;
      pb[(n0 + 1) * 10] = acc[u].y * QMUL;
      pb[(n0 + 2) * 10] = acc[u].z * QMUL;
      pb[(n0 + 3) * 10] = acc[u].w * QMUL;
    } else {
      float* pb = g_KV + (bh * 1024) * 20 + ((which == 1) ? d : 10 + d);
      pb[(n0 + 0) * 20] = acc[u].x;
      pb[(n0 + 1) * 20] = acc[u].y;
      pb[(n0 + 2) * 20] = acc[u].z;
      pb[(n0 + 3) * 20] = acc[u].w;
    }
  }
}

// ---------------- K3: attention, 2 queries/thread + split-K, rwb in smem ----------------
// smem: KV chunk 512*20 (40960B) + rwb 256*32 (32768B) + krh 630 + krw 630
#define ATTN_SMEM ((10240 + 8192 + 640 + 640) * 4)

__global__ void __launch_bounds__(256, 2) attn_kernel(const float* __restrict__ krh,
                                                      const float* __restrict__ krw) {
  extern __shared__ float sm[];
  float* KVs = sm;               // [512][20]
  float* RWb = sm + 10240;       // [xm][tid] rw for query B (thread-private slots)
  float* Hs  = sm + 18432;       // key_rel_h 63*10
  float* Ws  = sm + 19072;       // key_rel_w 63*10
  int bh = blockIdx.z;
  int kc = blockIdx.y;           // key chunk 0/1
  int tid = threadIdx.x;         // 256
  int warp = tid >> 5, lane = tid & 31;

  // stage KV chunk (coalesced float4 copy) + rel tables
  {
    const float4* src = (const float4*)(g_KV + bh * 20480 + kc * 10240);
    float4* dst = (float4*)KVs;
    #pragma unroll 10
    for (int i = tid; i < 2560; i += 256) dst[i] = src[i];
    for (int i = tid; i < 630; i += 256) { Hs[i] = krh[i]; Ws[i] = krw[i]; }
  }

  int ya = blockIdx.x * 16 + warp;     // query row A (warp 0..7)
  int yb = ya + 8;                     // query row B
  int xq = lane;
  int na = ya * 32 + xq, nb = yb * 32 + xq;
  const float* qa = g_Q + (bh * 1024 + na) * 10;   // pre-scaled by dkh^-.5*log2e
  const float* qb = g_Q + (bh * 1024 + nb) * 10;
  u64 Qa01 = ldf2(qa), Qa23 = ldf2(qa + 2), Qa45 = ldf2(qa + 4),
      Qa67 = ldf2(qa + 6), Qa89 = ldf2(qa + 8);
  u64 Qb01 = ldf2(qb), Qb23 = ldf2(qb + 2), Qb45 = ldf2(qb + 4),
      Qb67 = ldf2(qb + 6), Qb89 = ldf2(qb + 8);

  __syncthreads();

  // rw per query; A -> registers, B -> thread-private smem slot
  float rwa[32];
  #pragma unroll
  for (int xm = 0; xm < 32; xm++) {
    const float* kr = Ws + (xm - xq + 31) * 10;
    u64 k01 = ldf2(kr), k23 = ldf2(kr + 2), k45 = ldf2(kr + 4),
        k67 = ldf2(kr + 6), k89 = ldf2(kr + 8);
    u64 sa = fmul2(Qa01, k01);
    sa = ffma2(Qa23, k23, sa); sa = ffma2(Qa45, k45, sa);
    sa = ffma2(Qa67, k67, sa); sa = ffma2(Qa89, k89, sa);
    u64 sb = fmul2(Qb01, k01);
    sb = ffma2(Qb23, k23, sb); sb = ffma2(Qb45, k45, sb);
    sb = ffma2(Qb67, k67, sb); sb = ffma2(Qb89, k89, sb);
    float2 fa = unpack2(sa), fb = unpack2(sb);
    rwa[xm] = fa.x + fa.y;
    RWb[xm * 256 + tid] = fb.x + fb.y;   // [xm][tid]: lane-consecutive, conflict-free
  }

  u64 Aa01 = 0, Aa23 = 0, Aa45 = 0, Aa67 = 0, Aa89 = 0;
  u64 Ab01 = 0, Ab23 = 0, Ab45 = 0, Ab67 = 0, Ab89 = 0;
  float la = 0.f, lb = 0.f;
  #pragma unroll 1
  for (int ym16 = 0; ym16 < 16; ym16++) {
    int ymg = kc * 16 + ym16;
    const float* kha = Hs + (ymg - ya + 31) * 10;   // smem broadcast (row const per warp)
    const float* khb = Hs + (ymg - yb + 31) * 10;
    u64 ra = fmul2(Qa01, ldf2(kha));
    ra = ffma2(Qa23, ldf2(kha + 2), ra); ra = ffma2(Qa45, ldf2(kha + 4), ra);
    ra = ffma2(Qa67, ldf2(kha + 6), ra); ra = ffma2(Qa89, ldf2(kha + 8), ra);
    u64 rb = fmul2(Qb01, ldf2(khb));
    rb = ffma2(Qb23, ldf2(khb + 2), rb); rb = ffma2(Qb45, ldf2(khb + 4), rb);
    rb = ffma2(Qb67, ldf2(khb + 6), rb); rb = ffma2(Qb89, ldf2(khb + 8), rb);
    float2 fra = unpack2(ra), frb = unpack2(rb);
    float rha = fra.x + fra.y, rhb = frb.x + frb.y;

    const float4* kv = (const float4*)(KVs + ym16 * 640);
    #pragma unroll
    for (int xm = 0; xm < 32; xm++) {
      F4U c0, c1, c2, c3, c4;
      c0.f4 = kv[xm * 5];      // K0..K3
      c1.f4 = kv[xm * 5 + 1];  // K4..K7
      c2.f4 = kv[xm * 5 + 2];  // K8,K9,V0,V1
      c3.f4 = kv[xm * 5 + 3];  // V2..V5
      c4.f4 = kv[xm * 5 + 4];  // V6..V9
      float rwb = RWb[xm * 256 + tid];
      u64 sa = ffma2(Qa01, c0.u2.x, pack2(rha, rwa[xm]));
      sa = ffma2(Qa23, c0.u2.y, sa);
      sa = ffma2(Qa45, c1.u2.x, sa);
      sa = ffma2(Qa67, c1.u2.y, sa);
      sa = ffma2(Qa89, c2.u2.x, sa);
      u64 sb = ffma2(Qb01, c0.u2.x, pack2(rhb, rwb));
      sb = ffma2(Qb23, c0.u2.y, sb);
      sb = ffma2(Qb45, c1.u2.x, sb);
      sb = ffma2(Qb67, c1.u2.y, sb);
      sb = ffma2(Qb89, c2.u2.x, sb);
      float2 pa2 = unpack2(sa), pb2 = unpack2(sb);
      float pa = ex2f(pa2.x + pa2.y);   // logits tiny; no max-subtract needed
      float pb = ex2f(pb2.x + pb2.y);
      la += pa; lb += pb;
      u64 Pa = pack2(pa, pa), Pb = pack2(pb, pb);
      Aa01 = ffma2(Pa, c2.u2.y, Aa01);
      Aa23 = ffma2(Pa, c3.u2.x, Aa23);
      Aa45 = ffma2(Pa, c3.u2.y, Aa45);
      Aa67 = ffma2(Pa, c4.u2.x, Aa67);
      Aa89 = ffma2(Pa, c4.u2.y, Aa89);
      Ab01 = ffma2(Pb, c2.u2.y, Ab01);
      Ab23 = ffma2(Pb, c3.u2.x, Ab23);
      Ab45 = ffma2(Pb, c3.u2.y, Ab45);
      Ab67 = ffma2(Pb, c4.u2.x, Ab67);
      Ab89 = ffma2(Pb, c4.u2.y, Ab89);
    }
  }
  // store unnormalized partials (normalization in final_kernel)
  int base = (kc * 64 + bh) * 1024;
  u64* oa = (u64*)(g_pA + (base + na) * 10);
  oa[0] = Aa01; oa[1] = Aa23; oa[2] = Aa45; oa[3] = Aa67; oa[4] = Aa89;
  g_pl[base + na] = la;
  u64* ob = (u64*)(g_pA + (base + nb) * 10);
  ob[0] = Ab01; ob[1] = Ab23; ob[2] = Ab45; ob[3] = Ab67; ob[4] = Ab89;
  g_pl[base + nb] = lb;
}

// ---------------- K4: combine partials + poolconv + attno + fc ----------------
__global__ void final_kernel(const float* __restrict__ convo_w,
                             const float* __restrict__ convo_b,
                             const float* __restrict__ attno_w,
                             const float* __restrict__ attno_b,
                             const float* __restrict__ fc_w,
                             const float* __restrict__ fc_b,
                             float* __restrict__ out) {
  int b = blockIdx.x, tid = threadIdx.x;  // 256 threads
  int warp = tid >> 5, lane = tid & 31;
  __shared__ float Ssm[576];
  __shared__ float invl[4096];   // per (head,n) 1/(l0+l1)
  __shared__ float pooled[88];
  __shared__ float mean_s[40], pa[40];

  for (int i = tid; i < 576; i += 256) Ssm[i] = g_S[b * 576 + i];
  #pragma unroll 4
  for (int i = tid; i < 4096; i += 256) {
    float l0 = g_pl[b * 4096 + i];
    float l1 = g_pl[64 * 1024 + b * 4096 + i];
    invl[i] = __frcp_rn(l0 + l1);
  }
  __syncthreads();

  #pragma unroll
  for (int i = 0; i < 11; i++) {
    int oc = warp * 11 + i;
    float acc = 0.f;
    const float* wp = convo_w + oc * 576;
    #pragma unroll
    for (int j = lane; j < 576; j += 32) acc = fmaf(__ldg(&wp[j]), Ssm[j], acc);
    acc = wred(acc);
    if (lane == 0) pooled[oc] = __ldg(&convo_b[oc]) + acc * (1.f / 1024.f);
  }

  #pragma unroll
  for (int cc = 0; cc < 5; cc++) {
    int c = warp * 5 + cc;
    const float* pA0 = g_pA + b * 40960 + c * 1024;
    const float* pA1 = g_pA + 64 * 10240 + b * 40960 + c * 1024;
    int fbase = c * 1024;
    float s = 0.f;
    #pragma unroll 4
    for (int j = lane; j < 1024; j += 32) {
      float a = pA0[j] + pA1[j];
      s = fmaf(a, invl[(fbase + j) / 10], s);
    }
    s = wred(s);
    if (lane == 0) mean_s[c] = s * (1.f / 1024.f);
  }
  __syncthreads();
  if (tid < 40) {
    float acc = __ldg(&attno_b[tid]);
    #pragma unroll 4
    for (int c = 0; c < 40; c++) acc = fmaf(__ldg(&attno_w[tid * 40 + c]), mean_s[c], acc);
    pa[tid] = acc;
  }
  __syncthreads();
  if (tid < 100) {
    float acc = __ldg(&fc_b[tid]);
    const float* wp = fc_w + tid * 128;
    #pragma unroll 4
    for (int c = 0; c < 88; c++) acc = fmaf(__ldg(&wp[c]), pooled[c], acc);
    #pragma unroll 4
    for (int c = 0; c < 40; c++) acc = fmaf(__ldg(&wp[88 + c]), pa[c], acc);
    out[b * 100 + tid] = acc;
  }
}

// ---------------- launch ----------------
extern "C" void kernel_launch(void* const* d_in, const int* in_sizes, int n_in,
                              void* d_out, int out_size) {
  const float* x         = (const float*)d_in[0];
  const float* conv1_w   = (const float*)d_in[1];
  const float* conv1_b   = (const float*)d_in[2];
  const float* bn1_g     = (const float*)d_in[3];
  const float* bn1_b     = (const float*)d_in[4];
  const float* convo_w   = (const float*)d_in[5];
  const float* convo_b   = (const float*)d_in[6];
  const float* qkv_w     = (const float*)d_in[7];
  const float* qkv_b     = (const float*)d_in[8];
  const float* attno_w   = (const float*)d_in[9];
  const float* attno_b   = (const float*)d_in[10];
  const float* key_rel_h = (const float*)d_in[11];
  const float* key_rel_w = (const float*)d_in[12];
  const float* fc_w      = (const float*)d_in[13];
  const float* fc_b      = (const float*)d_in[14];
  float* out = (float*)d_out;

  cudaFuncSetAttribute(attn_kernel, cudaFuncAttributeMaxDynamicSharedMemorySize, ATTN_SMEM);

  conv1_kernel<<<dim3(64, 16), 256>>>(x, conv1_w, conv1_b);     // #0
  bnrelu_kernel<<<dim3(64, 16), 1024>>>(bn1_g, bn1_b);          // #1
  qkv_kernel<<<dim3(1, 15, 16), 256>>>(qkv_w, qkv_b);           // #2
  attn_kernel<<<dim3(2, 2, 64), 256, ATTN_SMEM>>>(key_rel_h, key_rel_w);  // #3 (profiled)
  final_kernel<<<16, 256>>>(convo_w, convo_b, attno_w, attno_b, fc_w, fc_b, out);
}